// round 15
// baseline (speedup 1.0000x reference)
#include <cuda_runtime.h>

#define T_STEPS 512
#define BATCH   1024
#define IND     64
#define HID     8

// ---------------------------------------------------------------------------
// helpers
// ---------------------------------------------------------------------------
__device__ __forceinline__ unsigned long long pk2(float lo, float hi) {
    unsigned long long r;
    asm("mov.b64 %0, {%1, %2};" : "=l"(r) : "f"(lo), "f"(hi));
    return r;
}
__device__ __forceinline__ unsigned long long fma2(unsigned long long a, unsigned long long b, unsigned long long c) {
    unsigned long long d;
    asm("fma.rn.f32x2 %0, %1, %2, %3;" : "=l"(d) : "l"(a), "l"(b), "l"(c));
    return d;
}
__device__ __forceinline__ void upk2(unsigned long long v, float& lo, float& hi) {
    asm("mov.b64 {%0, %1}, %2;" : "=f"(lo), "=f"(hi) : "l"(v));
}
__device__ __forceinline__ float tanhapx(float x) {
    float r; asm("tanh.approx.f32 %0, %1;" : "=f"(r) : "f"(x)); return r;
}

// ---------------------------------------------------------------------------
// Fused kernel: one warp per batch element (one warp per block -> all SMs).
// lane = g*8+j, quarter-split x, transpose-reduce projection.
// ck reduction via 3-shfl xor-butterfly (was 8-shfl gather + tree).
// ---------------------------------------------------------------------------
__global__ void __launch_bounds__(32) qlstm_kernel(
    const float* __restrict__ X,
    const float* __restrict__ Wf, const float* __restrict__ bf, const float* __restrict__ thf,
    const float* __restrict__ Wi_, const float* __restrict__ bi, const float* __restrict__ thi,
    const float* __restrict__ Wu, const float* __restrict__ bu, const float* __restrict__ thu,
    const float* __restrict__ Wo, const float* __restrict__ bo, const float* __restrict__ tho,
    const float* __restrict__ Wh2k, const float* __restrict__ bh2k,
    const float* __restrict__ Wi2k, const float* __restrict__ bi2k,
    float* __restrict__ out)
{
    const unsigned FULL = 0xffffffffu;
    int lane = threadIdx.x & 31;
    int b = blockIdx.x;            // 0..1023, one warp per batch
    int g = lane >> 3, j = lane & 7;
    int gb = lane & 24;
    int s0 = g & 1;
    int s1 = (g >> 1) & 1;

    const float* Wsel = (g == 0) ? Wf : (g == 1) ? Wi_ : (g == 2) ? Wu : Wo;

    int k0 = g * 16;               // this lane's quarter of k-space

    // quarter weights for ALL 4 gate columns at unit j
    unsigned long long WxQ[4][8];
    #pragma unroll
    for (int i = 0; i < 8; i++) {
        int k = k0 + 2 * i;
        WxQ[0][i] = pk2(__ldg(Wf  + k * 8 + j), __ldg(Wf  + (k + 1) * 8 + j));
        WxQ[1][i] = pk2(__ldg(Wi_ + k * 8 + j), __ldg(Wi_ + (k + 1) * 8 + j));
        WxQ[2][i] = pk2(__ldg(Wu  + k * 8 + j), __ldg(Wu  + (k + 1) * 8 + j));
        WxQ[3][i] = pk2(__ldg(Wo  + k * 8 + j), __ldg(Wo  + (k + 1) * 8 + j));
    }

    // s-dot quarter weights (own quarter, -0.5 folded)
    unsigned long long Wsq[8];
    #pragma unroll
    for (int i = 0; i < 8; i++) {
        int k = k0 + 2 * i;
        Wsq[i] = pk2(-0.5f * __ldg(Wi2k + k * 8 + j), -0.5f * __ldg(Wi2k + (k + 1) * 8 + j));
    }

    // recurrent weights
    float Wh[8], Wk[8];
    #pragma unroll
    for (int k = 0; k < 8; k++) {
        Wh[k] = __ldg(Wsel + (64 + k) * 8 + j);
        Wk[k] = 0.5f * __ldg(Wh2k + k * 8 + j);
    }

    // quarter-folded biases (reduce sums 4 quarters -> full bias)
    float qb0 = 0.25f * (__ldg(bf + j) + __ldg(thf + j));
    float qb1 = 0.25f * (__ldg(bi + j) + __ldg(thi + j));
    float qb2 = 0.25f * (__ldg(bu + j) + __ldg(thu + j));
    float qb3 = 0.25f * (__ldg(bo + j) + __ldg(tho + j));
    float sq0 = 0.125f * (__ldg(bh2k + j) - __ldg(bi2k + j));  // 0.25 * 0.5*(bh2k-bi2k)

    // activation: f,i,o -> sigmoid(m)=0.5+0.5*tanh(m/2); u -> tanh(m)
    float asc  = (g == 2) ? 1.f : 0.5f;
    float aoff = (g == 2) ? 0.f : 0.5f;
    float aarg = (g == 2) ? 1.f : 0.5f;

    float hk[8];
    #pragma unroll
    for (int k = 0; k < 8; k++) hk[k] = 0.f;
    float c = 0.f, hme = 0.f;

    float4 xq[4];   // this lane's quarter of the x row

    const size_t xstride = (size_t)BATCH * 16;    // float4 stride per time step
    const float4* xp = reinterpret_cast<const float4*>(X) + (size_t)b * 16 + g * 4;

#define LOADX_P() do {                                                          \
        _Pragma("unroll")                                                       \
        for (int i = 0; i < 4; i++) xq[i] = __ldg(xp + i);                      \
        xp += xstride;                                                          \
    } while (0)

#define PROJ(PX, PS) do {                                                       \
        unsigned long long a0 = pk2(qb0, 0.f), a1 = pk2(qb1, 0.f);              \
        unsigned long long a2 = pk2(qb2, 0.f), a3 = pk2(qb3, 0.f);              \
        unsigned long long as_ = pk2(sq0, 0.f);                                 \
        _Pragma("unroll")                                                       \
        for (int i = 0; i < 4; i++) {                                           \
            float4 xv = xq[i];                                                  \
            unsigned long long plo = pk2(xv.x, xv.y), phi = pk2(xv.z, xv.w);    \
            a0 = fma2(plo, WxQ[0][2 * i], a0);  a0 = fma2(phi, WxQ[0][2 * i + 1], a0); \
            a1 = fma2(plo, WxQ[1][2 * i], a1);  a1 = fma2(phi, WxQ[1][2 * i + 1], a1); \
            a2 = fma2(plo, WxQ[2][2 * i], a2);  a2 = fma2(phi, WxQ[2][2 * i + 1], a2); \
            a3 = fma2(plo, WxQ[3][2 * i], a3);  a3 = fma2(phi, WxQ[3][2 * i + 1], a3); \
            as_ = fma2(plo, Wsq[2 * i], as_);   as_ = fma2(phi, Wsq[2 * i + 1], as_);  \
        }                                                                       \
        float l0, h0, l1, h1, l2, h2, l3, h3, ls, hs;                           \
        upk2(a0, l0, h0); upk2(a1, l1, h1); upk2(a2, l2, h2); upk2(a3, l3, h3); \
        upk2(as_, ls, hs);                                                      \
        float p0 = l0 + h0, p1 = l1 + h1, p2 = l2 + h2, p3 = l3 + h3;           \
        float sendLo = s0 ? p0 : p1;                                            \
        float sendHi = s0 ? p2 : p3;                                            \
        float rLo = __shfl_xor_sync(FULL, sendLo, 8);                           \
        float rHi = __shfl_xor_sync(FULL, sendHi, 8);                           \
        float SLo = (s0 ? p1 : p0) + rLo;                                       \
        float SHi = (s0 ? p3 : p2) + rHi;                                       \
        float send2 = s1 ? SLo : SHi;                                           \
        float r2v = __shfl_xor_sync(FULL, send2, 16);                           \
        (PX) = (s1 ? SHi : SLo) + r2v;                                          \
        float sp = ls + hs;                                                     \
        sp += __shfl_xor_sync(FULL, sp, 8);                                     \
        sp += __shfl_xor_sync(FULL, sp, 16);                                    \
        (PS) = sp;                                                              \
    } while (0)

    // prologue
    float px_0, ps_0, px_1, ps_1;
    LOADX_P(); PROJ(px_0, ps_0);
    LOADX_P(); PROJ(px_1, ps_1);
    LOADX_P();                       // xq = row 2, xp -> row 3

    float* outp = out + (size_t)b * HID + j;
    const size_t ostride = (size_t)BATCH * HID;

    #pragma unroll 2
    for (int t = 0; t < T_STEPS; t++) {
        float px_2, ps_2;
        PROJ(px_2, ps_2);            // row t+2 (stale/unused for t>509)
        if (t < T_STEPS - 3) LOADX_P();

        // ---- chain step t ----
        float preA = px_0, preB = 0.f, kaA = ps_0, kaB = 0.f;
        #pragma unroll
        for (int k = 0; k < 4; k++) {
            preA = fmaf(hk[k],     Wh[k],     preA);
            preB = fmaf(hk[k + 4], Wh[k + 4], preB);
            kaA  = fmaf(hk[k],     Wk[k],     kaA);
            kaB  = fmaf(hk[k + 4], Wk[k + 4], kaB);
        }
        float z  = __cosf(preA + preB);
        float ck = __cosf(kaA + kaB);

        // z all-gather within the 8-lane gate group: 8 independent shfls
        float zk0 = __shfl_sync(FULL, z, gb | 0), zk1 = __shfl_sync(FULL, z, gb | 1);
        float zk2 = __shfl_sync(FULL, z, gb | 2), zk3 = __shfl_sync(FULL, z, gb | 3);
        float zk4 = __shfl_sync(FULL, z, gb | 4), zk5 = __shfl_sync(FULL, z, gb | 5);
        float zk6 = __shfl_sync(FULL, z, gb | 6), zk7 = __shfl_sync(FULL, z, gb | 7);

        // kernel weight via 3-shfl xor-butterfly product (ck identical across g)
        float w0 = ck * __shfl_xor_sync(FULL, ck, 1);
        float w1 = w0 * __shfl_xor_sync(FULL, w0, 2);
        float w2 = w1 * __shfl_xor_sync(FULL, w1, 4);
        float w  = fabsf(w2);

        // division-free qlayer product (shared-subterm tree + static SELs)
        float p01 = zk0 * zk1, p23 = zk2 * zk3, p45 = zk4 * zk5, p67 = zk6 * zk7;
        float q03 = p01 * p23, q47 = p45 * p67;
        float a0q = zk1 * p23;
        float pz6 = p45 * zk6;
        float m1 = (j == 0) ? a0q : ((j <= 2) ? p01 : q03);
        float m2 = (j == 0) ? q47 :
                   (j == 2) ? zk2 :
                   (j == 4) ? zk4 :
                   (j == 5) ? p45 :
                   (j == 6) ? pz6 :
                   (j == 7) ? q47 : 1.f;
        float r = m1 * m2;

        float val = fmaf(asc, tanhapx(r * (w * aarg)), aoff);

        float fv = __shfl_sync(FULL, val, j);
        float iv = __shfl_sync(FULL, val, 8 + j);
        float gv = __shfl_sync(FULL, val, 16 + j);
        float ov = __shfl_sync(FULL, val, 24 + j);

        c = fmaf(fv, c, iv * gv);
        hme = ov * tanhapx(c);

        if (g == 0) *outp = hme;     // outputs[t][b][j]
        outp += ostride;

        hk[0] = __shfl_sync(FULL, hme, 0); hk[1] = __shfl_sync(FULL, hme, 1);
        hk[2] = __shfl_sync(FULL, hme, 2); hk[3] = __shfl_sync(FULL, hme, 3);
        hk[4] = __shfl_sync(FULL, hme, 4); hk[5] = __shfl_sync(FULL, hme, 5);
        hk[6] = __shfl_sync(FULL, hme, 6); hk[7] = __shfl_sync(FULL, hme, 7);

        px_0 = px_1; ps_0 = ps_1;
        px_1 = px_2; ps_1 = ps_2;
    }

    if (g == 0) {
        out[(size_t)T_STEPS * BATCH * HID + (size_t)b * HID + j] = hme;
        out[(size_t)T_STEPS * BATCH * HID + (size_t)BATCH * HID + (size_t)b * HID + j] = c;
    }
#undef LOADX_P
#undef PROJ
}

// ---------------------------------------------------------------------------
// Launch: 1024 one-warp blocks -> work on all 148 SMs.
// ---------------------------------------------------------------------------
extern "C" void kernel_launch(void* const* d_in, const int* in_sizes, int n_in,
                              void* d_out, int out_size)
{
    const float* in[17];
    for (int i = 0; i < 17 && i < n_in; i++) in[i] = (const float*)d_in[i];

    int iIn, iWf, iBf, iTf, iWi, iBi, iTi, iWu, iBu, iTu, iWo, iBo, iTo,
        iWh2k, iBh2k, iWi2k, iBi2k;

    if (in_sizes[0] == T_STEPS * BATCH * IND) {
        iIn = 0; iWh2k = 13; iBh2k = 14; iWi2k = 15; iBi2k = 16;
        if (in_sizes[3] == 576) {
            iWf = 1; iBf = 2; iWi = 3; iBi = 4; iWu = 5; iBu = 6; iWo = 7; iBo = 8;
            iTf = 9; iTi = 10; iTu = 11; iTo = 12;
        } else {
            iWf = 1; iBf = 2; iTf = 3; iWi = 4; iBi = 5; iTi = 6;
            iWu = 7; iBu = 8; iTu = 9; iWo = 10; iBo = 11; iTo = 12;
        }
    } else {
        iWf = 0; iWh2k = 1; iWi = 2; iWi2k = 3; iWo = 4; iWu = 5;
        iBf = 6; iBh2k = 7; iBi = 8; iBi2k = 9; iBo = 10; iBu = 11;
        iIn = 12; iTf = 13; iTi = 14; iTo = 15; iTu = 16;
    }

    qlstm_kernel<<<BATCH, 32>>>(
        in[iIn],
        in[iWf], in[iBf], in[iTf],
        in[iWi], in[iBi], in[iTi],
        in[iWu], in[iBu], in[iTu],
        in[iWo], in[iBo], in[iTo],
        in[iWh2k], in[iBh2k], in[iWi2k], in[iBi2k],
        (float*)d_out);
}